// round 1
// baseline (speedup 1.0000x reference)
#include <cuda_runtime.h>
#include <math.h>

#define NWG   256     // waveguides
#define NP    128     // pairs per layer
#define NITER 3
#define TB    16      // batch rows per CTA in pipeline / rows per CTA in build_R

// ---------------- scratch (no allocations allowed) ----------------
// Folded MZI 2x2 matrices: per MZI two float4: {A.re,A.im,B.re,B.im}, {C.re,C.im,D.re,D.im}
__device__ float4 g_coef[NITER * NWG * NP * 2];          // 3 MB
// R[i][j][n] = (diag(e^{i gamma}) U_i)[n][j]  as complex float2, stored as float4 pairs
__device__ float4 g_R[NITER * NWG * NWG / 2];            // 1.5 MB

// ---------------- constants ----------------
#define HALF_G    0.07853981633974483f   // 0.5 * 0.05 * pi
#define HALF_PHIB 1.5707963267948966f    // 0.5 * pi
#define SQ09      0.9486832980505138f    // sqrt(1 - 0.1)

// ============================================================
// Kernel 1: fold theta/phi into 2x2 complex MZI matrices
// y0 = A x0 + B x1 ; y1 = C x0 + D x1
// A = pre*ep*s, B = pre*c, C = pre*ep*c, D = -pre*s
// pre = i e^{i h} = (-sin h, cos h), ep = e^{i phi}, h = theta/2
// Odd layers, pair 127 (wrap pair) is masked -> identity matrix.
// ============================================================
__global__ void coef_kernel(const float* __restrict__ theta,
                            const float* __restrict__ phi) {
    int t = blockIdx.x * blockDim.x + threadIdx.x;
    const int total = NITER * NWG * NP;
    if (t >= total) return;
    int pair  = t % NP;
    int layer = (t / NP) % NWG;

    float4 c01, c23;
    if ((layer & 1) && pair == NP - 1) {
        c01 = make_float4(1.f, 0.f, 0.f, 0.f);   // A=1, B=0
        c23 = make_float4(0.f, 0.f, 1.f, 0.f);   // C=0, D=1
    } else {
        float h = 0.5f * theta[t];
        float s, c;  sincosf(h, &s, &c);
        float sp, cp; sincosf(phi[t], &sp, &cp);
        float pre_r = -s, pre_i = c;                       // i*e^{ih}
        float pe_r = pre_r * cp - pre_i * sp;              // pre*ep
        float pe_i = pre_r * sp + pre_i * cp;
        c01 = make_float4(pe_r * s,  pe_i * s,   pre_r * c,  pre_i * c);   // A, B
        c23 = make_float4(pe_r * c,  pe_i * c,  -pre_r * s, -pre_i * s);   // C, D
    }
    g_coef[2 * t]     = c01;
    g_coef[2 * t + 1] = c23;
}

// ============================================================
// Kernel 2: build R_i by pushing the 256 identity basis vectors
// through the mesh of iteration i (+ gamma phases).
// grid = (256/TB, NITER), block = 512 threads.
// thread: pair p = tid & 127, row-group rg = tid >> 7 (4 rows each).
// smem layout: de-interleaved SoA (conflict-free stride-1 access).
// ============================================================
__global__ void build_R_kernel(const float* __restrict__ gamma) {
    __shared__ float x0r[TB][NP], x0i[TB][NP], x1r[TB][NP], x1i[TB][NP];
    const int iter = blockIdx.y;
    const int p  = threadIdx.x & (NP - 1);
    const int rg = threadIdx.x >> 7;       // 0..3
    const int rbase = rg * 4;
    const int growbase = blockIdx.x * TB;

    // identity init: row j is basis vector e_j
    #pragma unroll
    for (int i = 0; i < 4; i++) {
        int r = rbase + i;
        int gj = growbase + r;
        x0r[r][p] = (2 * p     == gj) ? 1.f : 0.f;  x0i[r][p] = 0.f;
        x1r[r][p] = (2 * p + 1 == gj) ? 1.f : 0.f;  x1i[r][p] = 0.f;
    }
    __syncthreads();

    const float4* cbase = g_coef + (size_t)iter * NWG * NP * 2;
    for (int l = 0; l < NWG; l++) {
        float4 c01 = cbase[(l * NP + p) * 2];
        float4 c23 = cbase[(l * NP + p) * 2 + 1];
        float Ar = c01.x, Ai = c01.y, Br = c01.z, Bi = c01.w;
        float Cr = c23.x, Ci = c23.y, Dr = c23.z, Di = c23.w;
        bool odd = l & 1;
        if (!odd) {
            #pragma unroll
            for (int i = 0; i < 4; i++) {
                int r = rbase + i;
                float ar = x0r[r][p], ai = x0i[r][p];
                float br = x1r[r][p], bi = x1i[r][p];
                float y0r = Ar*ar - Ai*ai + Br*br - Bi*bi;
                float y0i = Ar*ai + Ai*ar + Br*bi + Bi*br;
                float y1r = Cr*ar - Ci*ai + Dr*br - Di*bi;
                float y1i = Cr*ai + Ci*ar + Dr*bi + Di*br;
                x0r[r][p] = y0r; x0i[r][p] = y0i;
                x1r[r][p] = y1r; x1i[r][p] = y1i;
            }
        } else if (p < NP - 1) {
            // pair = (x[2p+1], x[2p+2]) = (x1[p], x0[p+1]); wrap pair p=127 masked (no-op)
            #pragma unroll
            for (int i = 0; i < 4; i++) {
                int r = rbase + i;
                float ar = x1r[r][p],     ai = x1i[r][p];
                float br = x0r[r][p + 1], bi = x0i[r][p + 1];
                float y0r = Ar*ar - Ai*ai + Br*br - Bi*bi;
                float y0i = Ar*ai + Ai*ar + Br*bi + Bi*br;
                float y1r = Cr*ar - Ci*ai + Dr*br - Di*bi;
                float y1i = Cr*ai + Ci*ar + Dr*bi + Di*br;
                x1r[r][p] = y0r;     x1i[r][p] = y0i;
                x0r[r][p + 1] = y1r; x0i[r][p + 1] = y1i;
            }
        }
        __syncthreads();
    }

    // gamma phases, then store R[iter][j][n] = mesh(e_j)[n]
    float s0, c0, s1, c1;
    sincosf(gamma[iter * NWG + 2 * p],     &s0, &c0);
    sincosf(gamma[iter * NWG + 2 * p + 1], &s1, &c1);
    float2* Rf2 = reinterpret_cast<float2*>(g_R);
    #pragma unroll
    for (int i = 0; i < 4; i++) {
        int r = rbase + i;
        int gj = growbase + r;
        size_t rowoff = ((size_t)iter * NWG + gj) * NWG;
        float xr = x0r[r][p], xi = x0i[r][p];
        Rf2[rowoff + 2 * p]     = make_float2(xr * c0 - xi * s0, xr * s0 + xi * c0);
        xr = x1r[r][p]; xi = x1i[r][p];
        Rf2[rowoff + 2 * p + 1] = make_float2(xr * c1 - xi * s1, xr * s1 + xi * c1);
    }
}

// ============================================================
// Kernel 3: fused batch pipeline.
// For each CTA: 16 batch rows resident in smem.
//   3x: X' = X @ R_i  (complex GEMM, 4x4 register tile per thread)
//       i<2: EO nonlinearity elementwise, write back
//       i=2: intensity, per-row L2 norm of intensity, write 10 cols.
// block = 256 threads: rg = tid>>6 (rows 4rg..4rg+3), cg = tid&63 (cols 4cg..4cg+3)
// ============================================================
__global__ __launch_bounds__(256) void pipeline_kernel(
        const float* __restrict__ xre, const float* __restrict__ xim,
        float* __restrict__ out) {
    __shared__ float2 Xs[TB][NWG];     // 32 KB
    __shared__ float  red[TB];
    const int tid = threadIdx.x;
    const int rowbase = blockIdx.x * TB;

    // load inputs
    for (int e = tid; e < TB * NWG; e += 256) {
        int r = e >> 8, n = e & (NWG - 1);
        Xs[r][n] = make_float2(xre[(rowbase + r) * NWG + n],
                               xim[(rowbase + r) * NWG + n]);
    }
    __syncthreads();

    const int cg = tid & 63, rg = tid >> 6;
    const int c0 = cg * 4, r0 = rg * 4;

    float accre[4][4], accim[4][4];

    for (int it = 0; it < NITER; it++) {
        #pragma unroll
        for (int i = 0; i < 4; i++)
            #pragma unroll
            for (int j = 0; j < 4; j++) { accre[i][j] = 0.f; accim[i][j] = 0.f; }

        const float4* Rb = g_R + (size_t)it * NWG * NWG / 2;
        #pragma unroll 4
        for (int k = 0; k < NWG; k++) {
            float2 xv[4];
            #pragma unroll
            for (int i = 0; i < 4; i++) xv[i] = Xs[r0 + i][k];   // broadcast LDS
            float4 rlo = Rb[(k * NWG + c0) >> 1];
            float4 rhi = Rb[((k * NWG + c0) >> 1) + 1];
            float rvr[4] = { rlo.x, rlo.z, rhi.x, rhi.z };
            float rvi[4] = { rlo.y, rlo.w, rhi.y, rhi.w };
            #pragma unroll
            for (int i = 0; i < 4; i++) {
                #pragma unroll
                for (int j = 0; j < 4; j++) {
                    accre[i][j] += xv[i].x * rvr[j];
                    accre[i][j] -= xv[i].y * rvi[j];
                    accim[i][j] += xv[i].x * rvi[j];
                    accim[i][j] += xv[i].y * rvr[j];
                }
            }
        }
        __syncthreads();   // all reads of Xs for this GEMM are done

        if (it != NITER - 1) {
            // EO nonlinearity: phase = 0.5*g*|x|^2 + 0.5*phi_b
            // out = sqrt(0.9) * cos(phase) * e^{-i phase} * x
            #pragma unroll
            for (int i = 0; i < 4; i++) {
                #pragma unroll
                for (int j = 0; j < 4; j++) {
                    float re = accre[i][j], im = accim[i][j];
                    float phase = HALF_G * (re * re + im * im) + HALF_PHIB;
                    float sp, cp; sincosf(phase, &sp, &cp);
                    float sc = SQ09 * cp;
                    Xs[r0 + i][c0 + j] = make_float2(sc * (cp * re + sp * im),
                                                     sc * (cp * im - sp * re));
                }
            }
            __syncthreads();
        }
    }

    // epilogue: intensity + normalize(intensity, L2 over row) + first 10 cols
    if (tid < TB) red[tid] = 0.f;
    __syncthreads();

    float v[4][4];
    #pragma unroll
    for (int i = 0; i < 4; i++) {
        float partial = 0.f;
        #pragma unroll
        for (int j = 0; j < 4; j++) {
            float re = accre[i][j], im = accim[i][j];
            v[i][j] = re * re + im * im;
            partial += v[i][j] * v[i][j];
        }
        atomicAdd(&red[r0 + i], partial);
    }
    __syncthreads();

    #pragma unroll
    for (int i = 0; i < 4; i++) {
        float inv = 1.f / fmaxf(sqrtf(red[r0 + i]), 1e-12f);
        #pragma unroll
        for (int j = 0; j < 4; j++) {
            int c = c0 + j;
            if (c < 10)
                out[(rowbase + r0 + i) * 10 + c] = v[i][j] * inv;
        }
    }
}

// ============================================================
extern "C" void kernel_launch(void* const* d_in, const int* in_sizes, int n_in,
                              void* d_out, int out_size) {
    const float* xre   = (const float*)d_in[0];
    const float* xim   = (const float*)d_in[1];
    const float* theta = (const float*)d_in[2];
    const float* phi   = (const float*)d_in[3];
    const float* gamma = (const float*)d_in[4];
    float* out = (float*)d_out;

    coef_kernel<<<(NITER * NWG * NP + 255) / 256, 256>>>(theta, phi);
    build_R_kernel<<<dim3(NWG / TB, NITER), 512>>>(gamma);
    pipeline_kernel<<<8192 / TB, 256>>>(xre, xim, out);
}